// round 1
// baseline (speedup 1.0000x reference)
#include <cuda_runtime.h>
#include <math.h>

#define B  32
#define T  20
#define C  512
#define P  196
#define H  1024
#define NC 101

// ---------------- device scratch (no allocations allowed) ----------------
__device__ float g_sA2pre[T * B * P];     // sum_c videos*W_sC21 + b_sC21 + spatialBias
__device__ float g_tC2pre[T * B * P];     // sum_c videos*W_tC21
__device__ float g_YT[C * B];             // Y transposed: [c][b]
__device__ float g_h1T[(T + 1) * H * B];  // h1 history, transposed [t][h][b]
__device__ float g_h2T[(T + 1) * H * B];  // h2 history, transposed [t][h][b]
__device__ float g_h2n[(T + 1) * B * H];  // h2 history, normal [t][b][h]
__device__ float g_c1[B * H];
__device__ float g_c2[B * H];
__device__ float g_beta[T * B];           // raw betas [t][b]
__device__ float g_betasT[B * T];         // softmaxed [b][t]
__device__ float g_hbarT[H * B];          // sum_t betasT*h2_t, transposed

__device__ __forceinline__ float sigm(float x) { return 1.0f / (1.0f + __expf(-x)); }
__device__ __forceinline__ float ftanh(float x) {
    // tanh(x) = 1 - 2/(exp(2x)+1); handles +/-inf limits correctly
    return 1.0f - 2.0f / (__expf(2.0f * x) + 1.0f);
}

// ---------------- init: broadcast (1,H) states to all batches ----------------
__global__ void init_kernel(const float* __restrict__ h1, const float* __restrict__ c1,
                            const float* __restrict__ h2, const float* __restrict__ c2) {
    int idx = blockIdx.x * blockDim.x + threadIdx.x;
    if (idx >= B * H) return;
    int b = idx / H, h = idx % H;
    g_h1T[h * B + b] = h1[h];
    g_h2T[h * B + b] = h2[h];
    g_h2n[b * H + h] = h2[h];
    g_c1[b * H + h]  = c1[h];
    g_c2[b * H + h]  = c2[h];
}

// ---------------- precompute sA2pre / tC2pre (one pass over videos) ----------------
__global__ void pre_kernel(const float* __restrict__ videos,
                           const float* __restrict__ W_s, const float* __restrict__ b_s,
                           const float* __restrict__ W_t, const float* __restrict__ spatialBias) {
    __shared__ float ws[C], wt[C];
    int tid = threadIdx.x;
    for (int c = tid; c < C; c += blockDim.x) { ws[c] = W_s[c]; wt[c] = W_t[c]; }
    __syncthreads();
    int bid = blockIdx.x;
    int b = bid / T, t = bid % T;
    int p = tid;
    if (p >= P) return;
    const float* vp = videos + ((size_t)(b * T + t) * C) * P + p;
    float accs = 0.f, acct = 0.f;
#pragma unroll 4
    for (int c = 0; c < C; c++) {
        float v = vp[(size_t)c * P];
        accs += v * ws[c];
        acct += v * wt[c];
    }
    int o = (t * B + b) * P + p;
    g_sA2pre[o] = accs + b_s[0] + spatialBias[p];
    g_tC2pre[o] = acct;
}

// ---------------- per-step attention: scores + softmax + beta ----------------
__global__ void attn_kernel(int t,
                            const float* __restrict__ W_h2p, const float* __restrict__ b_h2p,
                            const float* __restrict__ W_h21, const float* __restrict__ b_h21,
                            const float* __restrict__ b_tC21, const float* __restrict__ temporalBias,
                            float* __restrict__ alphas_out) {
    __shared__ float h2s[H];
    __shared__ float sc[P];
    __shared__ float red[8];
    int b = blockIdx.x, tid = threadIdx.x;
    int lane = tid & 31, w = tid >> 5;

    const float* h2p = g_h2n + (size_t)t * B * H + (size_t)b * H;
    for (int i = tid; i < H; i += 256) h2s[i] = h2p[i];
    __syncthreads();

    const float4* h4 = (const float4*)h2s;
    for (int p = w; p < P; p += 8) {
        const float4* wr = (const float4*)(W_h2p + (size_t)p * H);
        float acc = 0.f;
#pragma unroll
        for (int i = lane; i < H / 4; i += 32) {
            float4 a = wr[i], x = h4[i];
            acc += a.x * x.x + a.y * x.y + a.z * x.z + a.w * x.w;
        }
        for (int o = 16; o; o >>= 1) acc += __shfl_xor_sync(~0u, acc, o);
        if (lane == 0) sc[p] = acc + b_h2p[p] + g_sA2pre[(t * B + b) * P + p];
    }
    __syncthreads();

    // softmax over P
    float v = (tid < P) ? sc[tid] : -INFINITY;
    float m = v;
    for (int o = 16; o; o >>= 1) m = fmaxf(m, __shfl_xor_sync(~0u, m, o));
    if (lane == 0) red[w] = m;
    __syncthreads();
    m = red[0];
#pragma unroll
    for (int i = 1; i < 8; i++) m = fmaxf(m, red[i]);
    float e = (tid < P) ? __expf(v - m) : 0.f;
    float s = e;
    for (int o = 16; o; o >>= 1) s += __shfl_xor_sync(~0u, s, o);
    __syncthreads();
    if (lane == 0) red[w] = s;
    __syncthreads();
    s = red[0];
#pragma unroll
    for (int i = 1; i < 8; i++) s += red[i];
    float a = e / s;
    __syncthreads();
    if (tid < P) {
        sc[tid] = a;
        alphas_out[((size_t)t * B + b) * P + tid] = a;
    }
    __syncthreads();

    // beta = h2.W_h21 + dot(alpha, tC2pre) + consts
    float acc = 0.f;
    for (int i = tid; i < H; i += 256) acc += h2s[i] * W_h21[i];
    if (tid < P) acc += sc[tid] * g_tC2pre[(t * B + b) * P + tid];
    for (int o = 16; o; o >>= 1) acc += __shfl_xor_sync(~0u, acc, o);
    if (lane == 0) red[w] = acc;
    __syncthreads();
    if (tid == 0) {
        float sum = 0.f;
#pragma unroll
        for (int i = 0; i < 8; i++) sum += red[i];
        g_beta[t * B + b] = sum + b_h21[0] + b_tC21[0] + temporalBias[0];
    }
}

// ---------------- per-step Y[b,c] = sum_p alpha[b,p]*videos[b,t,c,p] ----------------
__global__ void y_kernel(int t, const float* __restrict__ videos, const float* __restrict__ alphas) {
    __shared__ float al[P];
    int b = blockIdx.y;
    int tid = threadIdx.x, lane = tid & 31, w = tid >> 5;
    for (int i = tid; i < P; i += 256) al[i] = alphas[((size_t)t * B + b) * P + i];
    __syncthreads();
    int c = blockIdx.x * 8 + w;
    const float* vp = videos + (((size_t)b * T + t) * C + c) * P;
    float acc = 0.f;
    for (int p = lane; p < P; p += 32) acc += al[p] * vp[p];
    for (int o = 16; o; o >>= 1) acc += __shfl_xor_sync(~0u, acc, o);
    if (lane == 0) g_YT[c * B + b] = acc;
}

// ---------------- fused LSTM gate + cell update: 1 warp per hidden unit, lane=batch ----
// MODE 0: LSTM1 (X1=YT K1=C, X2=h1T[t], out h1T[t+1], c1)
// MODE 1: LSTM2 (X1=h1T[t+1] K1=H, X2=h2T[t], out h2T[t+1]+h2n[t+1], c2)
template <int MODE>
__global__ void lstm_kernel(int t,
                            const float* __restrict__ Wih, const float* __restrict__ Whh,
                            const float* __restrict__ bih, const float* __restrict__ bhh) {
    constexpr int K1 = (MODE == 0) ? C : H;
    int h = blockIdx.x, lane = threadIdx.x;

    const float* X1 = (MODE == 0) ? g_YT : (g_h1T + (size_t)(t + 1) * H * B);
    const float* X2 = (MODE == 0) ? (g_h1T + (size_t)t * H * B) : (g_h2T + (size_t)t * H * B);
    float* cS = (MODE == 0) ? g_c1 : g_c2;

    float ai = bih[h]         + bhh[h];
    float af = bih[H + h]     + bhh[H + h];
    float ag = bih[2 * H + h] + bhh[2 * H + h];
    float ao = bih[3 * H + h] + bhh[3 * H + h];

    {
        const float4* wi = (const float4*)(Wih + (size_t)h * K1);
        const float4* wf = (const float4*)(Wih + (size_t)(H + h) * K1);
        const float4* wg = (const float4*)(Wih + (size_t)(2 * H + h) * K1);
        const float4* wo = (const float4*)(Wih + (size_t)(3 * H + h) * K1);
#pragma unroll 4
        for (int k4 = 0; k4 < K1 / 4; k4++) {
            float x0 = X1[(k4 * 4 + 0) * B + lane];
            float x1 = X1[(k4 * 4 + 1) * B + lane];
            float x2 = X1[(k4 * 4 + 2) * B + lane];
            float x3 = X1[(k4 * 4 + 3) * B + lane];
            float4 a = wi[k4]; ai += a.x * x0 + a.y * x1 + a.z * x2 + a.w * x3;
            float4 bq = wf[k4]; af += bq.x * x0 + bq.y * x1 + bq.z * x2 + bq.w * x3;
            float4 cq = wg[k4]; ag += cq.x * x0 + cq.y * x1 + cq.z * x2 + cq.w * x3;
            float4 dq = wo[k4]; ao += dq.x * x0 + dq.y * x1 + dq.z * x2 + dq.w * x3;
        }
    }
    {
        const float4* wi = (const float4*)(Whh + (size_t)h * H);
        const float4* wf = (const float4*)(Whh + (size_t)(H + h) * H);
        const float4* wg = (const float4*)(Whh + (size_t)(2 * H + h) * H);
        const float4* wo = (const float4*)(Whh + (size_t)(3 * H + h) * H);
#pragma unroll 4
        for (int k4 = 0; k4 < H / 4; k4++) {
            float x0 = X2[(k4 * 4 + 0) * B + lane];
            float x1 = X2[(k4 * 4 + 1) * B + lane];
            float x2 = X2[(k4 * 4 + 2) * B + lane];
            float x3 = X2[(k4 * 4 + 3) * B + lane];
            float4 a = wi[k4]; ai += a.x * x0 + a.y * x1 + a.z * x2 + a.w * x3;
            float4 bq = wf[k4]; af += bq.x * x0 + bq.y * x1 + bq.z * x2 + bq.w * x3;
            float4 cq = wg[k4]; ag += cq.x * x0 + cq.y * x1 + cq.z * x2 + cq.w * x3;
            float4 dq = wo[k4]; ao += dq.x * x0 + dq.y * x1 + dq.z * x2 + dq.w * x3;
        }
    }

    float i = sigm(ai);
    float f = sigm(af);
    float g = ftanh(ag);
    float o = sigm(ao);
    float c_old = cS[lane * H + h];
    float cn = f * c_old + i * g;
    float hn = o * ftanh(cn);
    cS[lane * H + h] = cn;
    if (MODE == 0) {
        g_h1T[(size_t)(t + 1) * H * B + h * B + lane] = hn;
    } else {
        g_h2T[(size_t)(t + 1) * H * B + h * B + lane] = hn;
        g_h2n[(size_t)(t + 1) * B * H + lane * H + h] = hn;
    }
}

// ---------------- betas softmax over time ----------------
__global__ void betasoft_kernel(float* __restrict__ betasT_out) {
    int b = threadIdx.x;  // 32 threads
    float v[T];
    float m = -INFINITY;
#pragma unroll
    for (int t = 0; t < T; t++) { v[t] = g_beta[t * B + b]; m = fmaxf(m, v[t]); }
    float s = 0.f;
#pragma unroll
    for (int t = 0; t < T; t++) { v[t] = __expf(v[t] - m); s += v[t]; }
    float inv = 1.f / s;
#pragma unroll
    for (int t = 0; t < T; t++) {
        float bt = v[t] * inv;
        g_betasT[b * T + t] = bt;
        betasT_out[b * T + t] = bt;
    }
}

// ---------------- hbar[b,:] = sum_t betasT[b,t] * h2_t[b,:] ----------------
__global__ void hbar_kernel() {
    int h = blockIdx.x, lane = threadIdx.x;
    float acc = 0.f;
#pragma unroll
    for (int t = 0; t < T; t++)
        acc += g_betasT[lane * T + t] * g_h2T[(size_t)(t + 1) * H * B + h * B + lane];
    g_hbarT[h * B + lane] = acc;
}

// ---------------- logits = hbar @ W_fc.T + b_fc ----------------
__global__ void logits_kernel(const float* __restrict__ W_fc, const float* __restrict__ b_fc,
                              float* __restrict__ out) {
    int nc = blockIdx.x, lane = threadIdx.x;
    float acc = b_fc[nc];
    const float4* wr = (const float4*)(W_fc + (size_t)nc * H);
#pragma unroll 4
    for (int k4 = 0; k4 < H / 4; k4++) {
        float4 a = wr[k4];
        acc += a.x * g_hbarT[(k4 * 4 + 0) * B + lane]
             + a.y * g_hbarT[(k4 * 4 + 1) * B + lane]
             + a.z * g_hbarT[(k4 * 4 + 2) * B + lane]
             + a.w * g_hbarT[(k4 * 4 + 3) * B + lane];
    }
    out[lane * NC + nc] = acc;
}

// ---------------- launch ----------------
extern "C" void kernel_launch(void* const* d_in, const int* in_sizes, int n_in,
                              void* d_out, int out_size) {
    const float* videos       = (const float*)d_in[0];
    const float* h1           = (const float*)d_in[1];
    const float* c1           = (const float*)d_in[2];
    const float* h2           = (const float*)d_in[3];
    const float* c2           = (const float*)d_in[4];
    const float* spatialBias  = (const float*)d_in[5];
    const float* temporalBias = (const float*)d_in[6];
    const float* W_h2p        = (const float*)d_in[7];
    const float* b_h2p        = (const float*)d_in[8];
    const float* W_sC21       = (const float*)d_in[9];
    const float* b_sC21       = (const float*)d_in[10];
    const float* W_h21        = (const float*)d_in[11];
    const float* b_h21        = (const float*)d_in[12];
    const float* W_tC21       = (const float*)d_in[13];
    const float* b_tC21       = (const float*)d_in[14];
    const float* Wih1         = (const float*)d_in[15];
    const float* Whh1         = (const float*)d_in[16];
    const float* bih1         = (const float*)d_in[17];
    const float* bhh1         = (const float*)d_in[18];
    const float* Wih2         = (const float*)d_in[19];
    const float* Whh2         = (const float*)d_in[20];
    const float* bih2         = (const float*)d_in[21];
    const float* bhh2         = (const float*)d_in[22];
    const float* W_fc         = (const float*)d_in[23];
    const float* b_fc         = (const float*)d_in[24];

    float* out        = (float*)d_out;
    float* logits_out = out;                                   // (B, NC)
    float* alphas_out = out + B * NC;                          // (T, B, P)
    float* betasT_out = out + B * NC + (size_t)T * B * P;      // (B, 1, T)

    init_kernel<<<(B * H + 255) / 256, 256>>>(h1, c1, h2, c2);
    pre_kernel<<<B * T, 224>>>(videos, W_sC21, b_sC21, W_tC21, spatialBias);

    for (int t = 0; t < T; t++) {
        attn_kernel<<<B, 256>>>(t, W_h2p, b_h2p, W_h21, b_h21, b_tC21, temporalBias, alphas_out);
        y_kernel<<<dim3(C / 8, B), 256>>>(t, videos, alphas_out);
        lstm_kernel<0><<<H, 32>>>(t, Wih1, Whh1, bih1, bhh1);
        lstm_kernel<1><<<H, 32>>>(t, Wih2, Whh2, bih2, bhh2);
    }

    betasoft_kernel<<<1, B>>>(betasT_out);
    hbar_kernel<<<H, 32>>>();
    logits_kernel<<<NC, 32>>>(W_fc, b_fc, logits_out);
}